// round 14
// baseline (speedup 1.0000x reference)
#include <cuda_runtime.h>
#include <cuda_fp16.h>
#include <math.h>
#include <stdint.h>

// Problem constants
#define Bn   16
#define Cc   384
#define Hh   28
#define Ww   28
#define Ll   784
#define Ff   384
#define Ee   384
#define FFNe 1536
#define NBk  12
#define NHd  8
#define WSz  7
#define Dh   48
#define Mrow (Bn*Ll)        // 12544

#define STAGES 4

// fp16 k-permutation: pair p=k>>1 within 16-pair (32-k) group -> p'=((p&3)<<2)|(p>>2)
__device__ __forceinline__ int pk16(int k) {
    int p = (k >> 1) & 15;
    int pp = ((p & 3) << 2) | (p >> 2);
    return (k & ~31) | (pp << 1) | (k & 1);
}
__device__ __forceinline__ uint32_t smem_u32(const void* p) {
    uint32_t a;
    asm("{ .reg .u64 t; cvta.to.shared.u64 t, %1; cvt.u32.u64 %0, t; }" : "=r"(a) : "l"(p));
    return a;
}
__device__ __forceinline__ void cp16(uint32_t dst, const void* src) {
    asm volatile("cp.async.cg.shared.global [%0], [%1], 16;" :: "r"(dst), "l"(src));
}
#define CP_COMMIT() asm volatile("cp.async.commit_group;" ::: "memory")
#define CP_WAIT1()  asm volatile("cp.async.wait_group 1;" ::: "memory")

__device__ __forceinline__ void mma_f16(float c[4],
    uint32_t a0, uint32_t a1, uint32_t a2, uint32_t a3, uint32_t b0, uint32_t b1)
{
    asm volatile("mma.sync.aligned.m16n8k16.row.col.f32.f16.f16.f32 "
        "{%0,%1,%2,%3}, {%4,%5,%6,%7}, {%8,%9}, {%0,%1,%2,%3};"
        : "+f"(c[0]), "+f"(c[1]), "+f"(c[2]), "+f"(c[3])
        : "r"(a0), "r"(a1), "r"(a2), "r"(a3), "r"(b0), "r"(b1));
}

// ---------------------------------------------------------------------------
// Scratch
// ---------------------------------------------------------------------------
__device__ __half g_xin[Mrow * (Ee + Cc)];   // fp16 permuted
__device__ float  g_h  [Mrow * Ff];          // fp32 residual
__device__ __half g_y  [Mrow * Ff];          // fp16 permuted (LN out / fused h-cvt)
__device__ __half g_qkv[Mrow * 3 * Ff];      // fp16 plain (attn input)
__device__ __half g_o  [Mrow * Ff];          // fp16 permuted (attn out)
__device__ __half g_mid[Mrow * FFNe];        // fp16 permuted (gelu out)

// weights: fp16, transposed to [N,K], k-permuted
#define W_IN_OFF    0
#define W_QKV_OFF   294912
#define W_PROJ_OFF  5603328
#define W_FFN1_OFF  7372800
#define W_FFN2_OFF  14450688
#define W_OUT_OFF   21528576
__device__ __half g_wt[21676032];

// ---------------------------------------------------------------------------
// Weight prep: src [K,N] fp32 -> dst [N, pk16(K)] fp16
// ---------------------------------------------------------------------------
__global__ void transpose_perm_k(const float* __restrict__ src, __half* __restrict__ dst,
                                 int K, int N)
{
    __shared__ float t[32][33];
    int mat = blockIdx.z;
    src += (size_t)mat * K * N;
    dst += (size_t)mat * K * N;
    int n0 = blockIdx.x * 32, k0 = blockIdx.y * 32;
    int tx = threadIdx.x, ty = threadIdx.y;
    #pragma unroll
    for (int i = ty; i < 32; i += 8)
        t[i][tx] = src[(size_t)(k0 + i) * N + n0 + tx];
    __syncthreads();
    #pragma unroll
    for (int i = ty; i < 32; i += 8)
        dst[(size_t)(n0 + i) * K + pk16(k0 + tx)] = __float2half(t[tx][i]);
}

// ---------------------------------------------------------------------------
// Build concatenated input [M, 768] fp16 permuted
// ---------------------------------------------------------------------------
__global__ void build_xin_k(const float* __restrict__ x,
                            const float* __restrict__ ew,
                            const float* __restrict__ eb)
{
    int idx = blockIdx.x * blockDim.x + threadIdx.x;
    if (idx >= Mrow * 768) return;
    int m = idx / 768, c = idx % 768;
    int b = m / Ll, l = m % Ll;
    float val;
    if (c < Ee) {
        float xn = 2.0f * (float)(l / Hh) / (float)(Ww - 1) - 1.0f;
        float yn = 2.0f * (float)(l % Hh) / (float)(Hh - 1) - 1.0f;
        val = sinf(xn * ew[c] + yn * ew[Ee + c] + eb[c]);
    } else {
        int cc = c - Ee;
        val = x[(size_t)b * Cc * Ll + (size_t)cc * Ll + l];
    }
    g_xin[(size_t)m * 768 + pk16(c)] = __float2half(val);
}

// ---------------------------------------------------------------------------
// fp16 mma GEMM with k16 software-pipelined fragments.
// CTA 128x128, 8 warps (warp 64x32), 4x k32 buffers, distance-3 cp.async,
// wait_group 1 (tile t+1 guaranteed complete inside iter t).
// Per iter: LDS(h1(t)) -> HMMA(h0(t)) -> LDS(h0(t+1)) -> HMMA(h1(t)) -> wait/sync.
// EPI: 0=store fp32, 1=gelu->fp16 permuted, 2=h += alpha*(v+bias),
//      3=transpose-out fp32, 4=store fp16 plain, 5=EPI2 + fp16-perm copy to g_y
// ---------------------------------------------------------------------------
template<int EPI>
__global__ __launch_bounds__(256)
void gemm_mma(const __half* __restrict__ A, const __half* __restrict__ Wt,
              const float* __restrict__ bias, float* __restrict__ C,
              int K, int N, const float* __restrict__ alpha_p)
{
    extern __shared__ __align__(16) __half sm[];
    __half* As = sm;                        // [STAGES][128][32] (8KB/stage)
    __half* Bs = sm + STAGES * 4096;
    uint32_t as_u = smem_u32(As), bs_u = smem_u32(Bs);

    int tid = threadIdx.x;
    int wid = tid >> 5, lane = tid & 31, tg = lane & 3, rw = lane >> 2;
    int wm = (wid & 1) * 64, wn = (wid >> 1) * 32;
    int n0 = blockIdx.x * 128, m0 = blockIdx.y * 128;

    const __half* Asrc0 = A  + (size_t)(m0 + (tid >> 2)) * K + (tid & 3) * 8;
    const __half* Asrc1 = A  + (size_t)(m0 + 64 + (tid >> 2)) * K + (tid & 3) * 8;
    const __half* Bsrc0 = Wt + (size_t)(n0 + (tid >> 2)) * K + (tid & 3) * 8;
    const __half* Bsrc1 = Wt + (size_t)(n0 + 64 + (tid >> 2)) * K + (tid & 3) * 8;
    uint32_t adst0 = as_u + tid * 16;
    uint32_t adst1 = as_u + tid * 16 + 4096;
    uint32_t bdst0 = bs_u + tid * 16;
    uint32_t bdst1 = bs_u + tid * 16 + 4096;

    float acc[4][4][4];
    #pragma unroll
    for (int a = 0; a < 4; a++)
        #pragma unroll
        for (int b = 0; b < 4; b++)
            #pragma unroll
            for (int c = 0; c < 4; c++) acc[a][b][c] = 0.0f;

    const int nt = K >> 5;   // >= 12 always

    // prologue: tiles 0..2
    #pragma unroll
    for (int s = 0; s < STAGES - 1; s++) {
        uint32_t so = (uint32_t)(s * 8192);
        cp16(adst0 + so, Asrc0 + s * 32);
        cp16(adst1 + so, Asrc1 + s * 32);
        cp16(bdst0 + so, Bsrc0 + s * 32);
        cp16(bdst1 + so, Bsrc1 + s * 32);
        CP_COMMIT();
    }

    CP_WAIT1();                 // tiles 0,1 complete
    __syncthreads();
    {   // issue tile 3 (slot 3)
        uint32_t so = (uint32_t)(3 * 8192);
        cp16(adst0 + so, Asrc0 + 3 * 32);
        cp16(adst1 + so, Asrc1 + 3 * 32);
        cp16(bdst0 + so, Bsrc0 + 3 * 32);
        cp16(bdst1 + so, Bsrc1 + 3 * 32);
        CP_COMMIT();
    }

    // fragment double buffers (uint2 per fragment per k16 half)
    uint2 xa0[4], xa1[4], xb[4];   // holds h0 of current tile
    uint2 ya0[4], ya1[4], yb[4];   // holds h1 of current tile

    // preload h0(0)
    {
        const __half* Ab = As;
        const __half* Bb = Bs;
        int off = tg * 8;
        #pragma unroll
        for (int mf = 0; mf < 4; mf++) {
            xa0[mf] = *reinterpret_cast<const uint2*>(Ab + (wm + mf * 16 + rw) * 32 + off);
            xa1[mf] = *reinterpret_cast<const uint2*>(Ab + (wm + mf * 16 + rw + 8) * 32 + off);
        }
        #pragma unroll
        for (int nf = 0; nf < 4; nf++)
            xb[nf] = *reinterpret_cast<const uint2*>(Bb + (wn + nf * 8 + rw) * 32 + off);
    }

    for (int t = 0; t < nt; t++) {
        const __half* Ab = As + (t & 3) * 4096;
        const __half* Bb = Bs + (t & 3) * 4096;

        // load h1(t)
        {
            int off = tg * 8 + 4;
            #pragma unroll
            for (int mf = 0; mf < 4; mf++) {
                ya0[mf] = *reinterpret_cast<const uint2*>(Ab + (wm + mf * 16 + rw) * 32 + off);
                ya1[mf] = *reinterpret_cast<const uint2*>(Ab + (wm + mf * 16 + rw + 8) * 32 + off);
            }
            #pragma unroll
            for (int nf = 0; nf < 4; nf++)
                yb[nf] = *reinterpret_cast<const uint2*>(Bb + (wn + nf * 8 + rw) * 32 + off);
        }

        // HMMA h0(t) — overlaps h1 loads
        #pragma unroll
        for (int mf = 0; mf < 4; mf++)
            #pragma unroll
            for (int nf = 0; nf < 4; nf++)
                mma_f16(acc[mf][nf], xa0[mf].x, xa1[mf].x, xa0[mf].y, xa1[mf].y,
                        xb[nf].x, xb[nf].y);

        // load h0(t+1) — tile t+1 complete (wait_group 1 at prior iter end)
        if (t + 1 < nt) {
            const __half* Abn = As + ((t + 1) & 3) * 4096;
            const __half* Bbn = Bs + ((t + 1) & 3) * 4096;
            int off = tg * 8;
            #pragma unroll
            for (int mf = 0; mf < 4; mf++) {
                xa0[mf] = *reinterpret_cast<const uint2*>(Abn + (wm + mf * 16 + rw) * 32 + off);
                xa1[mf] = *reinterpret_cast<const uint2*>(Abn + (wm + mf * 16 + rw + 8) * 32 + off);
            }
            #pragma unroll
            for (int nf = 0; nf < 4; nf++)
                xb[nf] = *reinterpret_cast<const uint2*>(Bbn + (wn + nf * 8 + rw) * 32 + off);
        }

        // HMMA h1(t) — overlaps h0(t+1) loads
        #pragma unroll
        for (int mf = 0; mf < 4; mf++)
            #pragma unroll
            for (int nf = 0; nf < 4; nf++)
                mma_f16(acc[mf][nf], ya0[mf].x, ya1[mf].x, ya0[mf].y, ya1[mf].y,
                        yb[nf].x, yb[nf].y);

        // advance pipeline: complete tile t+2, free slot t&3, issue tile t+4
        if (t + 1 < nt) {
            CP_WAIT1();
            __syncthreads();
            int tn = t + 4;
            if (tn < nt) {
                uint32_t so = (uint32_t)((tn & 3) * 8192);
                cp16(adst0 + so, Asrc0 + tn * 32);
                cp16(adst1 + so, Asrc1 + tn * 32);
                cp16(bdst0 + so, Bsrc0 + tn * 32);
                cp16(bdst1 + so, Bsrc1 + tn * 32);
            }
            CP_COMMIT();
        }
    }

    float alpha = (EPI == 2 || EPI == 5) ? *alpha_p : 0.0f;

    #pragma unroll
    for (int mf = 0; mf < 4; mf++) {
        int r0 = m0 + wm + mf * 16 + rw;
        #pragma unroll
        for (int nf = 0; nf < 4; nf++) {
            int col = n0 + wn + nf * 8 + 2 * tg;
            float bx = bias[col], by = bias[col + 1];
            float v0 = acc[mf][nf][0] + bx, v1 = acc[mf][nf][1] + by;
            float v2 = acc[mf][nf][2] + bx, v3 = acc[mf][nf][3] + by;
            if (EPI == 0) {
                *reinterpret_cast<float2*>(C + (size_t)r0 * N + col) = make_float2(v0, v1);
                *reinterpret_cast<float2*>(C + (size_t)(r0 + 8) * N + col) = make_float2(v2, v3);
            } else if (EPI == 1) {
                v0 = 0.5f * v0 * (1.0f + erff(v0 * 0.7071067811865475f));
                v1 = 0.5f * v1 * (1.0f + erff(v1 * 0.7071067811865475f));
                v2 = 0.5f * v2 * (1.0f + erff(v2 * 0.7071067811865475f));
                v3 = 0.5f * v3 * (1.0f + erff(v3 * 0.7071067811865475f));
                __half* Ch = reinterpret_cast<__half*>(C);
                int c0 = pk16(col), c1 = pk16(col + 1);
                Ch[(size_t)r0 * N + c0] = __float2half(v0);
                Ch[(size_t)r0 * N + c1] = __float2half(v1);
                Ch[(size_t)(r0 + 8) * N + c0] = __float2half(v2);
                Ch[(size_t)(r0 + 8) * N + c1] = __float2half(v3);
            } else if (EPI == 2 || EPI == 5) {
                float2 h0 = *reinterpret_cast<const float2*>(C + (size_t)r0 * N + col);
                float2 h1 = *reinterpret_cast<const float2*>(C + (size_t)(r0 + 8) * N + col);
                h0.x += alpha * v0; h0.y += alpha * v1;
                h1.x += alpha * v2; h1.y += alpha * v3;
                *reinterpret_cast<float2*>(C + (size_t)r0 * N + col) = h0;
                *reinterpret_cast<float2*>(C + (size_t)(r0 + 8) * N + col) = h1;
                if (EPI == 5) {
                    int c0 = pk16(col), c1 = pk16(col + 1);
                    g_y[(size_t)r0 * Ff + c0] = __float2half(h0.x);
                    g_y[(size_t)r0 * Ff + c1] = __float2half(h0.y);
                    g_y[(size_t)(r0 + 8) * Ff + c0] = __float2half(h1.x);
                    g_y[(size_t)(r0 + 8) * Ff + c1] = __float2half(h1.y);
                }
            } else if (EPI == 3) {
                int b0i = r0 / Ll, l0 = r0 % Ll;
                int b1i = (r0 + 8) / Ll, l1 = (r0 + 8) % Ll;
                C[(size_t)b0i * Cc * Ll + (size_t)col * Ll + l0] = v0;
                C[(size_t)b0i * Cc * Ll + (size_t)(col + 1) * Ll + l0] = v1;
                C[(size_t)b1i * Cc * Ll + (size_t)col * Ll + l1] = v2;
                C[(size_t)b1i * Cc * Ll + (size_t)(col + 1) * Ll + l1] = v3;
            } else { // EPI == 4: fp16 plain store
                __half* Ch = reinterpret_cast<__half*>(C);
                __half2* p0 = reinterpret_cast<__half2*>(Ch + (size_t)r0 * N + col);
                __half2* p1 = reinterpret_cast<__half2*>(Ch + (size_t)(r0 + 8) * N + col);
                *p0 = __floats2half2_rn(v0, v1);
                *p1 = __floats2half2_rn(v2, v3);
            }
        }
    }
}

// ---------------------------------------------------------------------------
// LayerNorm F=384: warp/token; output fp16 permuted
// ---------------------------------------------------------------------------
__global__ __launch_bounds__(256)
void ln_k(const float* __restrict__ x, const float* __restrict__ s,
          const float* __restrict__ bb, __half* __restrict__ y)
{
    int gw = (blockIdx.x * blockDim.x + threadIdx.x) >> 5;
    int lane = threadIdx.x & 31;
    if (gw >= Mrow) return;
    const float* xr = x + (size_t)gw * Ff;

    float v[12];
    float sum = 0.0f;
    #pragma unroll
    for (int i = 0; i < 12; i++) { v[i] = xr[lane + i * 32]; sum += v[i]; }
    #pragma unroll
    for (int o = 16; o > 0; o >>= 1) sum += __shfl_xor_sync(0xffffffffu, sum, o);
    float mean = sum * (1.0f / 384.0f);

    float var = 0.0f;
    #pragma unroll
    for (int i = 0; i < 12; i++) { float d = v[i] - mean; var += d * d; }
    #pragma unroll
    for (int o = 16; o > 0; o >>= 1) var += __shfl_xor_sync(0xffffffffu, var, o);
    var *= (1.0f / 384.0f);
    float rstd = rsqrtf(var + 1e-5f);

    __half* yr = y + (size_t)gw * Ff;
    #pragma unroll
    for (int i = 0; i < 12; i++) {
        int c = lane + i * 32;
        yr[pk16(c)] = __float2half((v[i] - mean) * rstd * s[c] + bb[c]);
    }
}

// ---------------------------------------------------------------------------
// Windowed attention; qkv fp16 plain in, o fp16 permuted out
// ---------------------------------------------------------------------------
__global__ __launch_bounds__(256)
void attn_k(const __half* __restrict__ qkv, __half* __restrict__ o)
{
    __shared__ float sh[WSz * 1152];
    __shared__ float sc[NHd][WSz * WSz];

    int bw = blockIdx.x;
    int m0 = bw * WSz;
    int tid = threadIdx.x;

    const uint4* src = reinterpret_cast<const uint4*>(qkv + (size_t)m0 * 1152);
    for (int i = tid; i < WSz * 1152 / 8; i += 256) {
        uint4 u = src[i];
        __half2 h0 = *reinterpret_cast<__half2*>(&u.x);
        __half2 h1 = *reinterpret_cast<__half2*>(&u.y);
        __half2 h2 = *reinterpret_cast<__half2*>(&u.z);
        __half2 h3 = *reinterpret_cast<__half2*>(&u.w);
        float* d = sh + i * 8;
        float2 f0 = __half22float2(h0), f1 = __half22float2(h1);
        float2 f2 = __half22float2(h2), f3 = __half22float2(h3);
        d[0] = f0.x; d[1] = f0.y; d[2] = f1.x; d[3] = f1.y;
        d[4] = f2.x; d[5] = f2.y; d[6] = f3.x; d[7] = f3.y;
    }
    __syncthreads();

    int h = tid >> 5, lane = tid & 31;
    const float scale = 0.14433756729740643f;

    for (int idx = lane; idx < WSz * WSz; idx += 32) {
        int i = idx / WSz, j = idx % WSz;
        const float* q = sh + i * 1152 + h * Dh;
        const float* k = sh + j * 1152 + Ff + h * Dh;
        float d = 0.0f;
        #pragma unroll
        for (int t = 0; t < Dh; t++) d = fmaf(q[t], k[t], d);
        sc[h][idx] = d * scale;
    }
    __syncwarp();

    if (lane < WSz) {
        float* r = sc[h] + lane * WSz;
        float mx = r[0];
        #pragma unroll
        for (int j = 1; j < WSz; j++) mx = fmaxf(mx, r[j]);
        float sum = 0.0f;
        #pragma unroll
        for (int j = 0; j < WSz; j++) { float e = expf(r[j] - mx); r[j] = e; sum += e; }
        float inv = 1.0f / sum;
        #pragma unroll
        for (int j = 0; j < WSz; j++) r[j] *= inv;
    }
    __syncwarp();

    for (int idx = lane; idx < WSz * Dh; idx += 32) {
        int i = idx / Dh, d = idx % Dh;
        float a = 0.0f;
        #pragma unroll
        for (int j = 0; j < WSz; j++)
            a = fmaf(sc[h][i * WSz + j], sh[j * 1152 + 2 * Ff + h * Dh + d], a);
        o[(size_t)(m0 + i) * Ff + pk16(h * Dh + d)] = __float2half(a);
    }
}

// ---------------------------------------------------------------------------
// Launch — ncu captures launch index 3 (0-based) = gemm_in
// ---------------------------------------------------------------------------
extern "C" void kernel_launch(void* const* d_in, const int* in_sizes, int n_in,
                              void* d_out, int out_size)
{
    const float* x       = (const float*)d_in[0];
    const float* embed_w = (const float*)d_in[1];
    const float* embed_b = (const float*)d_in[2];
    const float* in_w    = (const float*)d_in[3];
    const float* in_b    = (const float*)d_in[4];
    const float* ln1_s   = (const float*)d_in[5];
    const float* ln1_b   = (const float*)d_in[6];
    const float* qkv_w   = (const float*)d_in[7];
    const float* qkv_b   = (const float*)d_in[8];
    const float* proj_w  = (const float*)d_in[9];
    const float* proj_b  = (const float*)d_in[10];
    const float* ln2_s   = (const float*)d_in[11];
    const float* ln2_b   = (const float*)d_in[12];
    const float* ffn_w1  = (const float*)d_in[13];
    const float* ffn_b1  = (const float*)d_in[14];
    const float* ffn_w2  = (const float*)d_in[15];
    const float* ffn_b2  = (const float*)d_in[16];
    const float* re_alpha= (const float*)d_in[17];
    const float* out_w   = (const float*)d_in[18];
    const float* out_b   = (const float*)d_in[19];
    float* out = (float*)d_out;

    __half *xin, *y, *o, *mid, *wt, *qkv;
    float *h;
    cudaGetSymbolAddress((void**)&xin, g_xin);
    cudaGetSymbolAddress((void**)&h,   g_h);
    cudaGetSymbolAddress((void**)&y,   g_y);
    cudaGetSymbolAddress((void**)&qkv, g_qkv);
    cudaGetSymbolAddress((void**)&o,   g_o);
    cudaGetSymbolAddress((void**)&mid, g_mid);
    cudaGetSymbolAddress((void**)&wt,  g_wt);

    const int SMSZ = STAGES * 4096 * 2 * 2;   // 65536 bytes
    cudaFuncSetAttribute(gemm_mma<0>, cudaFuncAttributeMaxDynamicSharedMemorySize, SMSZ);
    cudaFuncSetAttribute(gemm_mma<1>, cudaFuncAttributeMaxDynamicSharedMemorySize, SMSZ);
    cudaFuncSetAttribute(gemm_mma<2>, cudaFuncAttributeMaxDynamicSharedMemorySize, SMSZ);
    cudaFuncSetAttribute(gemm_mma<3>, cudaFuncAttributeMaxDynamicSharedMemorySize, SMSZ);
    cudaFuncSetAttribute(gemm_mma<4>, cudaFuncAttributeMaxDynamicSharedMemorySize, SMSZ);
    cudaFuncSetAttribute(gemm_mma<5>, cudaFuncAttributeMaxDynamicSharedMemorySize, SMSZ);

    const int MT = Mrow / 128;   // 98
    const int LN_BLOCKS = Mrow * 32 / 256;
    dim3 tb(32, 8);

    // 0: build_xin
    build_xin_k<<<(Mrow * 768 + 255) / 256, 256>>>(x, embed_w, embed_b);
    // 1: transpose in_w
    transpose_perm_k<<<dim3(Ff/32, (Ee+Cc)/32, 1), tb>>>(in_w, wt + W_IN_OFF, Ee + Cc, Ff);
    // 2: transpose qkv_w
    transpose_perm_k<<<dim3(3*Ff/32, Ff/32, 12), tb>>>(qkv_w, wt + W_QKV_OFF, Ff, 3 * Ff);
    // 3: input projection  <-- ncu capture target
    gemm_mma<0><<<dim3(Ff / 128, MT), 256, SMSZ>>>(xin, wt + W_IN_OFF, in_b, h, Ee + Cc, Ff, nullptr);
    // 4: ln1 blk0
    ln_k<<<LN_BLOCKS, 256>>>(h, ln1_s, ln1_b, y);
    // 5: qkv GEMM blk0
    gemm_mma<4><<<dim3(3 * Ff / 128, MT), 256, SMSZ>>>(
        y, wt + W_QKV_OFF, qkv_b, (float*)qkv, Ff, 3 * Ff, nullptr);

    transpose_perm_k<<<dim3(Ff/32,   Ff/32,   12), tb>>>(proj_w, wt + W_PROJ_OFF, Ff, Ff);
    transpose_perm_k<<<dim3(FFNe/32, Ff/32,   12), tb>>>(ffn_w1, wt + W_FFN1_OFF, Ff, FFNe);
    transpose_perm_k<<<dim3(Ff/32,   FFNe/32, 12), tb>>>(ffn_w2, wt + W_FFN2_OFF, FFNe, Ff);
    transpose_perm_k<<<dim3(Cc/32,   Ff/32,   1),  tb>>>(out_w,  wt + W_OUT_OFF,  Ff, Cc);

    for (int blk = 0; blk < NBk; blk++) {
        if (blk > 0) {
            ln_k<<<LN_BLOCKS, 256>>>(h, ln1_s + blk * Ff, ln1_b + blk * Ff, y);
            gemm_mma<4><<<dim3(3 * Ff / 128, MT), 256, SMSZ>>>(
                y, wt + W_QKV_OFF + (size_t)blk * Ff * 3 * Ff, qkv_b + (size_t)blk * 3 * Ff,
                (float*)qkv, Ff, 3 * Ff, nullptr);
        }

        attn_k<<<Bn * (Ll / WSz), 256>>>(qkv, o);

        gemm_mma<2><<<dim3(Ff / 128, MT), 256, SMSZ>>>(
            o, wt + W_PROJ_OFF + (size_t)blk * Ff * Ff, proj_b + (size_t)blk * Ff,
            h, Ff, Ff, re_alpha + blk);

        ln_k<<<LN_BLOCKS, 256>>>(h, ln2_s + blk * Ff, ln2_b + blk * Ff, y);

        gemm_mma<1><<<dim3(FFNe / 128, MT), 256, SMSZ>>>(
            y, wt + W_FFN1_OFF + (size_t)blk * Ff * FFNe, ffn_b1 + (size_t)blk * FFNe,
            (float*)mid, Ff, FFNe, nullptr);

        if (blk == NBk - 1) {
            gemm_mma<5><<<dim3(Ff / 128, MT), 256, SMSZ>>>(
                mid, wt + W_FFN2_OFF + (size_t)blk * FFNe * Ff, ffn_b2 + (size_t)blk * Ff,
                h, FFNe, Ff, re_alpha + blk);
        } else {
            gemm_mma<2><<<dim3(Ff / 128, MT), 256, SMSZ>>>(
                mid, wt + W_FFN2_OFF + (size_t)blk * FFNe * Ff, ffn_b2 + (size_t)blk * Ff,
                h, FFNe, Ff, re_alpha + blk);
        }
    }

    // output projection + transpose to [B, C, H, W]
    gemm_mma<3><<<dim3(Cc / 128, MT), 256, SMSZ>>>(y, wt + W_OUT_OFF, out_b, out, Ff, Cc, nullptr);
}

// round 15
// speedup vs baseline: 1.1251x; 1.1251x over previous
#include <cuda_runtime.h>
#include <cuda_fp16.h>
#include <math.h>
#include <stdint.h>

// Problem constants
#define Bn   16
#define Cc   384
#define Hh   28
#define Ww   28
#define Ll   784
#define Ff   384
#define Ee   384
#define FFNe 1536
#define NBk  12
#define NHd  8
#define WSz  7
#define Dh   48
#define Mrow (Bn*Ll)        // 12544

#define STAGES 4
// per-stage: A [128][32] = 4096 halfs (8KB); B [64][32] = 2048 halfs (4KB)

// fp16 k-permutation: pair p=k>>1 within 16-pair (32-k) group -> p'=((p&3)<<2)|(p>>2)
__device__ __forceinline__ int pk16(int k) {
    int p = (k >> 1) & 15;
    int pp = ((p & 3) << 2) | (p >> 2);
    return (k & ~31) | (pp << 1) | (k & 1);
}
__device__ __forceinline__ uint32_t smem_u32(const void* p) {
    uint32_t a;
    asm("{ .reg .u64 t; cvta.to.shared.u64 t, %1; cvt.u32.u64 %0, t; }" : "=r"(a) : "l"(p));
    return a;
}
__device__ __forceinline__ void cp16(uint32_t dst, const void* src) {
    asm volatile("cp.async.cg.shared.global [%0], [%1], 16;" :: "r"(dst), "l"(src));
}
#define CP_COMMIT() asm volatile("cp.async.commit_group;" ::: "memory")
#define CP_WAIT2()  asm volatile("cp.async.wait_group 2;" ::: "memory")

__device__ __forceinline__ void mma_f16(float c[4],
    uint32_t a0, uint32_t a1, uint32_t a2, uint32_t a3, uint32_t b0, uint32_t b1)
{
    asm volatile("mma.sync.aligned.m16n8k16.row.col.f32.f16.f16.f32 "
        "{%0,%1,%2,%3}, {%4,%5,%6,%7}, {%8,%9}, {%0,%1,%2,%3};"
        : "+f"(c[0]), "+f"(c[1]), "+f"(c[2]), "+f"(c[3])
        : "r"(a0), "r"(a1), "r"(a2), "r"(a3), "r"(b0), "r"(b1));
}

// ---------------------------------------------------------------------------
// Scratch
// ---------------------------------------------------------------------------
__device__ __half g_xin[Mrow * (Ee + Cc)];   // fp16 permuted
__device__ float  g_h  [Mrow * Ff];          // fp32 residual
__device__ __half g_y  [Mrow * Ff];          // fp16 permuted (LN out / fused h-cvt)
__device__ __half g_qkv[Mrow * 3 * Ff];      // fp16 plain (attn input)
__device__ __half g_o  [Mrow * Ff];          // fp16 permuted (attn out)
__device__ __half g_mid[Mrow * FFNe];        // fp16 permuted (gelu out)

// weights: fp16, transposed to [N,K], k-permuted
#define W_IN_OFF    0
#define W_QKV_OFF   294912
#define W_PROJ_OFF  5603328
#define W_FFN1_OFF  7372800
#define W_FFN2_OFF  14450688
#define W_OUT_OFF   21528576
__device__ __half g_wt[21676032];

// ---------------------------------------------------------------------------
// Weight prep: src [K,N] fp32 -> dst [N, pk16(K)] fp16
// ---------------------------------------------------------------------------
__global__ void transpose_perm_k(const float* __restrict__ src, __half* __restrict__ dst,
                                 int K, int N)
{
    __shared__ float t[32][33];
    int mat = blockIdx.z;
    src += (size_t)mat * K * N;
    dst += (size_t)mat * K * N;
    int n0 = blockIdx.x * 32, k0 = blockIdx.y * 32;
    int tx = threadIdx.x, ty = threadIdx.y;
    #pragma unroll
    for (int i = ty; i < 32; i += 8)
        t[i][tx] = src[(size_t)(k0 + i) * N + n0 + tx];
    __syncthreads();
    #pragma unroll
    for (int i = ty; i < 32; i += 8)
        dst[(size_t)(n0 + i) * K + pk16(k0 + tx)] = __float2half(t[tx][i]);
}

// ---------------------------------------------------------------------------
// Build concatenated input [M, 768] fp16 permuted
// ---------------------------------------------------------------------------
__global__ void build_xin_k(const float* __restrict__ x,
                            const float* __restrict__ ew,
                            const float* __restrict__ eb)
{
    int idx = blockIdx.x * blockDim.x + threadIdx.x;
    if (idx >= Mrow * 768) return;
    int m = idx / 768, c = idx % 768;
    int b = m / Ll, l = m % Ll;
    float val;
    if (c < Ee) {
        float xn = 2.0f * (float)(l / Hh) / (float)(Ww - 1) - 1.0f;
        float yn = 2.0f * (float)(l % Hh) / (float)(Hh - 1) - 1.0f;
        val = sinf(xn * ew[c] + yn * ew[Ee + c] + eb[c]);
    } else {
        int cc = c - Ee;
        val = x[(size_t)b * Cc * Ll + (size_t)cc * Ll + l];
    }
    g_xin[(size_t)m * 768 + pk16(c)] = __float2half(val);
}

// ---------------------------------------------------------------------------
// fp16 mma GEMM: C[M,N] = A[M,Kperm] @ Wt[N,Kperm]^T + bias (f32 accum)
// CTA tile 128x64, 8 warps (4x2), warp tile 32x32 — small footprint for
// 3 CTAs/SM (~37% occ). R6-proven pipeline: 4x k32 buffers, distance-3
// cp.async, wait_group 2, one sync per tile, single uint4 fragment loads.
// EPI: 0=store fp32, 1=gelu->fp16 permuted, 2=h += alpha*(v+bias),
//      3=transpose-out fp32, 4=store fp16 plain, 5=EPI2 + fp16-perm copy to g_y
// ---------------------------------------------------------------------------
template<int EPI>
__global__ __launch_bounds__(256, 3)
void gemm_mma(const __half* __restrict__ A, const __half* __restrict__ Wt,
              const float* __restrict__ bias, float* __restrict__ C,
              int K, int N, const float* __restrict__ alpha_p)
{
    extern __shared__ __align__(16) __half sm[];
    __half* As = sm;                        // [STAGES][128][32] (8KB/stage)
    __half* Bs = sm + STAGES * 4096;        // [STAGES][64][32]  (4KB/stage)
    uint32_t as_u = smem_u32(As), bs_u = smem_u32(Bs);

    int tid = threadIdx.x;
    int wid = tid >> 5, lane = tid & 31, tg = lane & 3, rw = lane >> 2;
    int wm = (wid & 3) * 32, wn = (wid >> 2) * 32;
    int n0 = blockIdx.x * 64, m0 = blockIdx.y * 128;

    // cp.async: 512 A-chunks + 256 B-chunks per tile, 3 per thread
    const __half* Asrc0 = A  + (size_t)(m0 + (tid >> 2)) * K + (tid & 3) * 8;
    const __half* Asrc1 = A  + (size_t)(m0 + 64 + (tid >> 2)) * K + (tid & 3) * 8;
    const __half* Bsrc  = Wt + (size_t)(n0 + (tid >> 2)) * K + (tid & 3) * 8;
    uint32_t adst0 = as_u + tid * 16;
    uint32_t adst1 = as_u + tid * 16 + 4096;
    uint32_t bdst  = bs_u + tid * 16;

    float acc[2][4][4];
    #pragma unroll
    for (int a = 0; a < 2; a++)
        #pragma unroll
        for (int b = 0; b < 4; b++)
            #pragma unroll
            for (int c = 0; c < 4; c++) acc[a][b][c] = 0.0f;

    const int nt = K >> 5;

    #pragma unroll
    for (int s = 0; s < STAGES - 1; s++) {
        cp16(adst0 + (uint32_t)(s * 8192), Asrc0 + s * 32);
        cp16(adst1 + (uint32_t)(s * 8192), Asrc1 + s * 32);
        cp16(bdst  + (uint32_t)(s * 4096), Bsrc  + s * 32);
        CP_COMMIT();
    }

    for (int t = 0; t < nt; t++) {
        CP_WAIT2();
        __syncthreads();

        int tn = t + STAGES - 1;
        if (tn < nt) {
            cp16(adst0 + (uint32_t)((tn & 3) * 8192), Asrc0 + tn * 32);
            cp16(adst1 + (uint32_t)((tn & 3) * 8192), Asrc1 + tn * 32);
            cp16(bdst  + (uint32_t)((tn & 3) * 4096), Bsrc  + tn * 32);
        }
        CP_COMMIT();

        const __half* Ab = As + (t & 3) * 4096;
        const __half* Bb = Bs + (t & 3) * 2048;

        uint4 av0[2], av1[2], bv[4];
        #pragma unroll
        for (int mf = 0; mf < 2; mf++) {
            av0[mf] = *reinterpret_cast<const uint4*>(Ab + (wm + mf * 16 + rw) * 32 + tg * 8);
            av1[mf] = *reinterpret_cast<const uint4*>(Ab + (wm + mf * 16 + rw + 8) * 32 + tg * 8);
        }
        #pragma unroll
        for (int nf = 0; nf < 4; nf++)
            bv[nf] = *reinterpret_cast<const uint4*>(Bb + (wn + nf * 8 + rw) * 32 + tg * 8);

        #pragma unroll
        for (int mf = 0; mf < 2; mf++)
            #pragma unroll
            for (int nf = 0; nf < 4; nf++) {
                mma_f16(acc[mf][nf], av0[mf].x, av1[mf].x, av0[mf].y, av1[mf].y,
                        bv[nf].x, bv[nf].y);
                mma_f16(acc[mf][nf], av0[mf].z, av1[mf].z, av0[mf].w, av1[mf].w,
                        bv[nf].z, bv[nf].w);
            }
    }

    float alpha = (EPI == 2 || EPI == 5) ? *alpha_p : 0.0f;

    #pragma unroll
    for (int mf = 0; mf < 2; mf++) {
        int r0 = m0 + wm + mf * 16 + rw;
        #pragma unroll
        for (int nf = 0; nf < 4; nf++) {
            int col = n0 + wn + nf * 8 + 2 * tg;
            float bx = bias[col], by = bias[col + 1];
            float v0 = acc[mf][nf][0] + bx, v1 = acc[mf][nf][1] + by;
            float v2 = acc[mf][nf][2] + bx, v3 = acc[mf][nf][3] + by;
            if (EPI == 0) {
                *reinterpret_cast<float2*>(C + (size_t)r0 * N + col) = make_float2(v0, v1);
                *reinterpret_cast<float2*>(C + (size_t)(r0 + 8) * N + col) = make_float2(v2, v3);
            } else if (EPI == 1) {
                v0 = 0.5f * v0 * (1.0f + erff(v0 * 0.7071067811865475f));
                v1 = 0.5f * v1 * (1.0f + erff(v1 * 0.7071067811865475f));
                v2 = 0.5f * v2 * (1.0f + erff(v2 * 0.7071067811865475f));
                v3 = 0.5f * v3 * (1.0f + erff(v3 * 0.7071067811865475f));
                __half* Ch = reinterpret_cast<__half*>(C);
                int c0 = pk16(col), c1 = pk16(col + 1);
                Ch[(size_t)r0 * N + c0] = __float2half(v0);
                Ch[(size_t)r0 * N + c1] = __float2half(v1);
                Ch[(size_t)(r0 + 8) * N + c0] = __float2half(v2);
                Ch[(size_t)(r0 + 8) * N + c1] = __float2half(v3);
            } else if (EPI == 2 || EPI == 5) {
                float2 h0 = *reinterpret_cast<const float2*>(C + (size_t)r0 * N + col);
                float2 h1 = *reinterpret_cast<const float2*>(C + (size_t)(r0 + 8) * N + col);
                h0.x += alpha * v0; h0.y += alpha * v1;
                h1.x += alpha * v2; h1.y += alpha * v3;
                *reinterpret_cast<float2*>(C + (size_t)r0 * N + col) = h0;
                *reinterpret_cast<float2*>(C + (size_t)(r0 + 8) * N + col) = h1;
                if (EPI == 5) {
                    int c0 = pk16(col), c1 = pk16(col + 1);
                    g_y[(size_t)r0 * Ff + c0] = __float2half(h0.x);
                    g_y[(size_t)r0 * Ff + c1] = __float2half(h0.y);
                    g_y[(size_t)(r0 + 8) * Ff + c0] = __float2half(h1.x);
                    g_y[(size_t)(r0 + 8) * Ff + c1] = __float2half(h1.y);
                }
            } else if (EPI == 3) {
                int b0i = r0 / Ll, l0 = r0 % Ll;
                int b1i = (r0 + 8) / Ll, l1 = (r0 + 8) % Ll;
                C[(size_t)b0i * Cc * Ll + (size_t)col * Ll + l0] = v0;
                C[(size_t)b0i * Cc * Ll + (size_t)(col + 1) * Ll + l0] = v1;
                C[(size_t)b1i * Cc * Ll + (size_t)col * Ll + l1] = v2;
                C[(size_t)b1i * Cc * Ll + (size_t)(col + 1) * Ll + l1] = v3;
            } else { // EPI == 4: fp16 plain store
                __half* Ch = reinterpret_cast<__half*>(C);
                __half2* p0 = reinterpret_cast<__half2*>(Ch + (size_t)r0 * N + col);
                __half2* p1 = reinterpret_cast<__half2*>(Ch + (size_t)(r0 + 8) * N + col);
                *p0 = __floats2half2_rn(v0, v1);
                *p1 = __floats2half2_rn(v2, v3);
            }
        }
    }
}

// ---------------------------------------------------------------------------
// LayerNorm F=384: warp/token; output fp16 permuted
// ---------------------------------------------------------------------------
__global__ __launch_bounds__(256)
void ln_k(const float* __restrict__ x, const float* __restrict__ s,
          const float* __restrict__ bb, __half* __restrict__ y)
{
    int gw = (blockIdx.x * blockDim.x + threadIdx.x) >> 5;
    int lane = threadIdx.x & 31;
    if (gw >= Mrow) return;
    const float* xr = x + (size_t)gw * Ff;

    float v[12];
    float sum = 0.0f;
    #pragma unroll
    for (int i = 0; i < 12; i++) { v[i] = xr[lane + i * 32]; sum += v[i]; }
    #pragma unroll
    for (int o = 16; o > 0; o >>= 1) sum += __shfl_xor_sync(0xffffffffu, sum, o);
    float mean = sum * (1.0f / 384.0f);

    float var = 0.0f;
    #pragma unroll
    for (int i = 0; i < 12; i++) { float d = v[i] - mean; var += d * d; }
    #pragma unroll
    for (int o = 16; o > 0; o >>= 1) var += __shfl_xor_sync(0xffffffffu, var, o);
    var *= (1.0f / 384.0f);
    float rstd = rsqrtf(var + 1e-5f);

    __half* yr = y + (size_t)gw * Ff;
    #pragma unroll
    for (int i = 0; i < 12; i++) {
        int c = lane + i * 32;
        yr[pk16(c)] = __float2half((v[i] - mean) * rstd * s[c] + bb[c]);
    }
}

// ---------------------------------------------------------------------------
// Windowed attention; qkv fp16 plain in, o fp16 permuted out
// ---------------------------------------------------------------------------
__global__ __launch_bounds__(256)
void attn_k(const __half* __restrict__ qkv, __half* __restrict__ o)
{
    __shared__ float sh[WSz * 1152];
    __shared__ float sc[NHd][WSz * WSz];

    int bw = blockIdx.x;
    int m0 = bw * WSz;
    int tid = threadIdx.x;

    const uint4* src = reinterpret_cast<const uint4*>(qkv + (size_t)m0 * 1152);
    for (int i = tid; i < WSz * 1152 / 8; i += 256) {
        uint4 u = src[i];
        __half2 h0 = *reinterpret_cast<__half2*>(&u.x);
        __half2 h1 = *reinterpret_cast<__half2*>(&u.y);
        __half2 h2 = *reinterpret_cast<__half2*>(&u.z);
        __half2 h3 = *reinterpret_cast<__half2*>(&u.w);
        float* d = sh + i * 8;
        float2 f0 = __half22float2(h0), f1 = __half22float2(h1);
        float2 f2 = __half22float2(h2), f3 = __half22float2(h3);
        d[0] = f0.x; d[1] = f0.y; d[2] = f1.x; d[3] = f1.y;
        d[4] = f2.x; d[5] = f2.y; d[6] = f3.x; d[7] = f3.y;
    }
    __syncthreads();

    int h = tid >> 5, lane = tid & 31;
    const float scale = 0.14433756729740643f;

    for (int idx = lane; idx < WSz * WSz; idx += 32) {
        int i = idx / WSz, j = idx % WSz;
        const float* q = sh + i * 1152 + h * Dh;
        const float* k = sh + j * 1152 + Ff + h * Dh;
        float d = 0.0f;
        #pragma unroll
        for (int t = 0; t < Dh; t++) d = fmaf(q[t], k[t], d);
        sc[h][idx] = d * scale;
    }
    __syncwarp();

    if (lane < WSz) {
        float* r = sc[h] + lane * WSz;
        float mx = r[0];
        #pragma unroll
        for (int j = 1; j < WSz; j++) mx = fmaxf(mx, r[j]);
        float sum = 0.0f;
        #pragma unroll
        for (int j = 0; j < WSz; j++) { float e = expf(r[j] - mx); r[j] = e; sum += e; }
        float inv = 1.0f / sum;
        #pragma unroll
        for (int j = 0; j < WSz; j++) r[j] *= inv;
    }
    __syncwarp();

    for (int idx = lane; idx < WSz * Dh; idx += 32) {
        int i = idx / Dh, d = idx % Dh;
        float a = 0.0f;
        #pragma unroll
        for (int j = 0; j < WSz; j++)
            a = fmaf(sc[h][i * WSz + j], sh[j * 1152 + 2 * Ff + h * Dh + d], a);
        o[(size_t)(m0 + i) * Ff + pk16(h * Dh + d)] = __float2half(a);
    }
}

// ---------------------------------------------------------------------------
// Launch — ncu captures launch index 3 (0-based) = gemm_in
// ---------------------------------------------------------------------------
extern "C" void kernel_launch(void* const* d_in, const int* in_sizes, int n_in,
                              void* d_out, int out_size)
{
    const float* x       = (const float*)d_in[0];
    const float* embed_w = (const float*)d_in[1];
    const float* embed_b = (const float*)d_in[2];
    const float* in_w    = (const float*)d_in[3];
    const float* in_b    = (const float*)d_in[4];
    const float* ln1_s   = (const float*)d_in[5];
    const float* ln1_b   = (const float*)d_in[6];
    const float* qkv_w   = (const float*)d_in[7];
    const float* qkv_b   = (const float*)d_in[8];
    const float* proj_w  = (const float*)d_in[9];
    const float* proj_b  = (const float*)d_in[10];
    const float* ln2_s   = (const float*)d_in[11];
    const float* ln2_b   = (const float*)d_in[12];
    const float* ffn_w1  = (const float*)d_in[13];
    const float* ffn_b1  = (const float*)d_in[14];
    const float* ffn_w2  = (const float*)d_in[15];
    const float* ffn_b2  = (const float*)d_in[16];
    const float* re_alpha= (const float*)d_in[17];
    const float* out_w   = (const float*)d_in[18];
    const float* out_b   = (const float*)d_in[19];
    float* out = (float*)d_out;

    __half *xin, *y, *o, *mid, *wt, *qkv;
    float *h;
    cudaGetSymbolAddress((void**)&xin, g_xin);
    cudaGetSymbolAddress((void**)&h,   g_h);
    cudaGetSymbolAddress((void**)&y,   g_y);
    cudaGetSymbolAddress((void**)&qkv, g_qkv);
    cudaGetSymbolAddress((void**)&o,   g_o);
    cudaGetSymbolAddress((void**)&mid, g_mid);
    cudaGetSymbolAddress((void**)&wt,  g_wt);

    const int SMSZ = STAGES * (8192 + 4096);   // 49152 bytes
    cudaFuncSetAttribute(gemm_mma<0>, cudaFuncAttributeMaxDynamicSharedMemorySize, SMSZ);
    cudaFuncSetAttribute(gemm_mma<1>, cudaFuncAttributeMaxDynamicSharedMemorySize, SMSZ);
    cudaFuncSetAttribute(gemm_mma<2>, cudaFuncAttributeMaxDynamicSharedMemorySize, SMSZ);
    cudaFuncSetAttribute(gemm_mma<3>, cudaFuncAttributeMaxDynamicSharedMemorySize, SMSZ);
    cudaFuncSetAttribute(gemm_mma<4>, cudaFuncAttributeMaxDynamicSharedMemorySize, SMSZ);
    cudaFuncSetAttribute(gemm_mma<5>, cudaFuncAttributeMaxDynamicSharedMemorySize, SMSZ);

    const int MT = Mrow / 128;   // 98
    const int LN_BLOCKS = Mrow * 32 / 256;
    dim3 tb(32, 8);

    // 0: build_xin
    build_xin_k<<<(Mrow * 768 + 255) / 256, 256>>>(x, embed_w, embed_b);
    // 1: transpose in_w
    transpose_perm_k<<<dim3(Ff/32, (Ee+Cc)/32, 1), tb>>>(in_w, wt + W_IN_OFF, Ee + Cc, Ff);
    // 2: transpose qkv_w
    transpose_perm_k<<<dim3(3*Ff/32, Ff/32, 12), tb>>>(qkv_w, wt + W_QKV_OFF, Ff, 3 * Ff);
    // 3: input projection  <-- ncu capture target
    gemm_mma<0><<<dim3(Ff / 64, MT), 256, SMSZ>>>(xin, wt + W_IN_OFF, in_b, h, Ee + Cc, Ff, nullptr);
    // 4: ln1 blk0
    ln_k<<<LN_BLOCKS, 256>>>(h, ln1_s, ln1_b, y);
    // 5: qkv GEMM blk0
    gemm_mma<4><<<dim3(3 * Ff / 64, MT), 256, SMSZ>>>(
        y, wt + W_QKV_OFF, qkv_b, (float*)qkv, Ff, 3 * Ff, nullptr);

    transpose_perm_k<<<dim3(Ff/32,   Ff/32,   12), tb>>>(proj_w, wt + W_PROJ_OFF, Ff, Ff);
    transpose_perm_k<<<dim3(FFNe/32, Ff/32,   12), tb>>>(ffn_w1, wt + W_FFN1_OFF, Ff, FFNe);
    transpose_perm_k<<<dim3(Ff/32,   FFNe/32, 12), tb>>>(ffn_w2, wt + W_FFN2_OFF, FFNe, Ff);
    transpose_perm_k<<<dim3(Cc/32,   Ff/32,   1),  tb>>>(out_w,  wt + W_OUT_OFF,  Ff, Cc);

    for (int blk = 0; blk < NBk; blk++) {
        if (blk > 0) {
            ln_k<<<LN_BLOCKS, 256>>>(h, ln1_s + blk * Ff, ln1_b + blk * Ff, y);
            gemm_mma<4><<<dim3(3 * Ff / 64, MT), 256, SMSZ>>>(
                y, wt + W_QKV_OFF + (size_t)blk * Ff * 3 * Ff, qkv_b + (size_t)blk * 3 * Ff,
                (float*)qkv, Ff, 3 * Ff, nullptr);
        }

        attn_k<<<Bn * (Ll / WSz), 256>>>(qkv, o);

        gemm_mma<2><<<dim3(Ff / 64, MT), 256, SMSZ>>>(
            o, wt + W_PROJ_OFF + (size_t)blk * Ff * Ff, proj_b + (size_t)blk * Ff,
            h, Ff, Ff, re_alpha + blk);

        ln_k<<<LN_BLOCKS, 256>>>(h, ln2_s + blk * Ff, ln2_b + blk * Ff, y);

        gemm_mma<1><<<dim3(FFNe / 64, MT), 256, SMSZ>>>(
            y, wt + W_FFN1_OFF + (size_t)blk * Ff * FFNe, ffn_b1 + (size_t)blk * FFNe,
            (float*)mid, Ff, FFNe, nullptr);

        if (blk == NBk - 1) {
            gemm_mma<5><<<dim3(Ff / 64, MT), 256, SMSZ>>>(
                mid, wt + W_FFN2_OFF + (size_t)blk * FFNe * Ff, ffn_b2 + (size_t)blk * Ff,
                h, FFNe, Ff, re_alpha + blk);
        } else {
            gemm_mma<2><<<dim3(Ff / 64, MT), 256, SMSZ>>>(
                mid, wt + W_FFN2_OFF + (size_t)blk * FFNe * Ff, ffn_b2 + (size_t)blk * Ff,
                h, FFNe, Ff, re_alpha + blk);
        }
    }

    // output projection + transpose to [B, C, H, W]
    gemm_mma<3><<<dim3(Cc / 64, MT), 256, SMSZ>>>(y, wt + W_OUT_OFF, out_b, out, Ff, Cc, nullptr);
}

// round 16
// speedup vs baseline: 1.4019x; 1.2461x over previous
#include <cuda_runtime.h>
#include <cuda_fp16.h>
#include <math.h>
#include <stdint.h>

// Problem constants
#define Bn   16
#define Cc   384
#define Hh   28
#define Ww   28
#define Ll   784
#define Ff   384
#define Ee   384
#define FFNe 1536
#define NBk  12
#define NHd  8
#define WSz  7
#define Dh   48
#define Mrow (Bn*Ll)        // 12544

#define STAGES 4

// fp16 k-permutation: pair p=k>>1 within 16-pair (32-k) group -> p'=((p&3)<<2)|(p>>2)
__device__ __forceinline__ int pk16(int k) {
    int p = (k >> 1) & 15;
    int pp = ((p & 3) << 2) | (p >> 2);
    return (k & ~31) | (pp << 1) | (k & 1);
}
__device__ __forceinline__ uint32_t smem_u32(const void* p) {
    uint32_t a;
    asm("{ .reg .u64 t; cvta.to.shared.u64 t, %1; cvt.u32.u64 %0, t; }" : "=r"(a) : "l"(p));
    return a;
}
__device__ __forceinline__ void cp16(uint32_t dst, const void* src) {
    asm volatile("cp.async.cg.shared.global [%0], [%1], 16;" :: "r"(dst), "l"(src));
}
#define CP_COMMIT() asm volatile("cp.async.commit_group;" ::: "memory")
#define CP_WAIT2()  asm volatile("cp.async.wait_group 2;" ::: "memory")

__device__ __forceinline__ void mma_f16(float c[4],
    uint32_t a0, uint32_t a1, uint32_t a2, uint32_t a3, uint32_t b0, uint32_t b1)
{
    asm volatile("mma.sync.aligned.m16n8k16.row.col.f32.f16.f16.f32 "
        "{%0,%1,%2,%3}, {%4,%5,%6,%7}, {%8,%9}, {%0,%1,%2,%3};"
        : "+f"(c[0]), "+f"(c[1]), "+f"(c[2]), "+f"(c[3])
        : "r"(a0), "r"(a1), "r"(a2), "r"(a3), "r"(b0), "r"(b1));
}

// ---------------------------------------------------------------------------
// Scratch
// ---------------------------------------------------------------------------
__device__ __half g_xin[Mrow * (Ee + Cc)];   // fp16 permuted
__device__ float  g_h  [Mrow * Ff];          // fp32 residual
__device__ __half g_y  [Mrow * Ff];          // fp16 permuted (LN out / fused h-cvt)
__device__ __half g_qkv[Mrow * 3 * Ff];      // fp16 plain (attn input)
__device__ __half g_o  [Mrow * Ff];          // fp16 permuted (attn out)
__device__ __half g_mid[Mrow * FFNe];        // fp16 permuted (gelu out)

// weights: fp16, transposed to [N,K], k-permuted
#define W_IN_OFF    0
#define W_QKV_OFF   294912
#define W_PROJ_OFF  5603328
#define W_FFN1_OFF  7372800
#define W_FFN2_OFF  14450688
#define W_OUT_OFF   21528576
__device__ __half g_wt[21676032];

// ---------------------------------------------------------------------------
// Transpose body: src [K,N] fp32 (single matrix) -> dst [N, pk16(K)] fp16
// blockDim = (32, 8)
// ---------------------------------------------------------------------------
__device__ __forceinline__ void tp_body(const float* __restrict__ src,
                                        __half* __restrict__ dst,
                                        int K, int N, int n0, int k0)
{
    __shared__ float t[32][33];
    int tx = threadIdx.x, ty = threadIdx.y;
    #pragma unroll
    for (int i = ty; i < 32; i += 8)
        t[i][tx] = src[(size_t)(k0 + i) * N + n0 + tx];
    __syncthreads();
    #pragma unroll
    for (int i = ty; i < 32; i += 8)
        dst[(size_t)(n0 + i) * K + pk16(k0 + tx)] = __float2half(t[tx][i]);
}

// group 0: in (288 blocks) + qkv (5184) + proj (1728) = 7200 blocks
__global__ void transpose_grp0(const float* __restrict__ in_w,
                               const float* __restrict__ qkv_w,
                               const float* __restrict__ proj_w,
                               __half* __restrict__ wt)
{
    int bid = blockIdx.x;
    if (bid < 288) {
        // in: K=768, N=384, nx=12
        int n0 = (bid % 12) * 32, k0 = (bid / 12) * 32;
        tp_body(in_w, wt + W_IN_OFF, 768, 384, n0, k0);
    } else if (bid < 288 + 5184) {
        // qkv: K=384, N=1152, nx=36, per-mat 432
        int r = bid - 288;
        int mat = r / 432, rem = r % 432;
        int n0 = (rem % 36) * 32, k0 = (rem / 36) * 32;
        tp_body(qkv_w + (size_t)mat * 384 * 1152,
                wt + W_QKV_OFF + (size_t)mat * 384 * 1152, 384, 1152, n0, k0);
    } else {
        // proj: K=384, N=384, nx=12, per-mat 144
        int r = bid - 288 - 5184;
        int mat = r / 144, rem = r % 144;
        int n0 = (rem % 12) * 32, k0 = (rem / 12) * 32;
        tp_body(proj_w + (size_t)mat * 384 * 384,
                wt + W_PROJ_OFF + (size_t)mat * 384 * 384, 384, 384, n0, k0);
    }
}
#define GRP0_BLOCKS 7200

// group 1: ffn1 (6912) + ffn2 (6912) + out (144) = 13968 blocks
__global__ void transpose_grp1(const float* __restrict__ ffn_w1,
                               const float* __restrict__ ffn_w2,
                               const float* __restrict__ out_w,
                               __half* __restrict__ wt)
{
    int bid = blockIdx.x;
    if (bid < 6912) {
        // ffn1: K=384, N=1536, nx=48, per-mat 576
        int mat = bid / 576, rem = bid % 576;
        int n0 = (rem % 48) * 32, k0 = (rem / 48) * 32;
        tp_body(ffn_w1 + (size_t)mat * 384 * 1536,
                wt + W_FFN1_OFF + (size_t)mat * 384 * 1536, 384, 1536, n0, k0);
    } else if (bid < 13824) {
        // ffn2: K=1536, N=384, nx=12, per-mat 576
        int r = bid - 6912;
        int mat = r / 576, rem = r % 576;
        int n0 = (rem % 12) * 32, k0 = (rem / 12) * 32;
        tp_body(ffn_w2 + (size_t)mat * 1536 * 384,
                wt + W_FFN2_OFF + (size_t)mat * 1536 * 384, 1536, 384, n0, k0);
    } else {
        // out: K=384, N=384, nx=12
        int r = bid - 13824;
        int n0 = (r % 12) * 32, k0 = (r / 12) * 32;
        tp_body(out_w, wt + W_OUT_OFF, 384, 384, n0, k0);
    }
}
#define GRP1_BLOCKS 13968

// ---------------------------------------------------------------------------
// Build concatenated input [M, 768] fp16 permuted
// ---------------------------------------------------------------------------
__global__ void build_xin_k(const float* __restrict__ x,
                            const float* __restrict__ ew,
                            const float* __restrict__ eb)
{
    int idx = blockIdx.x * blockDim.x + threadIdx.x;
    if (idx >= Mrow * 768) return;
    int m = idx / 768, c = idx % 768;
    int b = m / Ll, l = m % Ll;
    float val;
    if (c < Ee) {
        float xn = 2.0f * (float)(l / Hh) / (float)(Ww - 1) - 1.0f;
        float yn = 2.0f * (float)(l % Hh) / (float)(Hh - 1) - 1.0f;
        val = sinf(xn * ew[c] + yn * ew[Ee + c] + eb[c]);
    } else {
        int cc = c - Ee;
        val = x[(size_t)b * Cc * Ll + (size_t)cc * Ll + l];
    }
    g_xin[(size_t)m * 768 + pk16(c)] = __float2half(val);
}

// ---------------------------------------------------------------------------
// fp16 mma GEMM (R13 best-known config, verbatim):
// CTA 128x128, 8 warps (warp 64x32), 4x k32 buffers, distance-3 prefetch,
// wait_group 2, one sync per k32 tile.
// EPI: 0=store fp32, 1=gelu->fp16 permuted, 2=h += alpha*(v+bias),
//      3=transpose-out fp32, 4=store fp16 plain, 5=EPI2 + fp16-perm copy to g_y
// ---------------------------------------------------------------------------
template<int EPI>
__global__ __launch_bounds__(256)
void gemm_mma(const __half* __restrict__ A, const __half* __restrict__ Wt,
              const float* __restrict__ bias, float* __restrict__ C,
              int K, int N, const float* __restrict__ alpha_p)
{
    extern __shared__ __align__(16) __half sm[];
    __half* As = sm;                        // [STAGES][128][32] (8KB/stage)
    __half* Bs = sm + STAGES * 4096;
    uint32_t as_u = smem_u32(As), bs_u = smem_u32(Bs);

    int tid = threadIdx.x;
    int wid = tid >> 5, lane = tid & 31, tg = lane & 3, rw = lane >> 2;
    int wm = (wid & 1) * 64, wn = (wid >> 1) * 32;
    int n0 = blockIdx.x * 128, m0 = blockIdx.y * 128;

    const __half* Asrc0 = A  + (size_t)(m0 + (tid >> 2)) * K + (tid & 3) * 8;
    const __half* Asrc1 = A  + (size_t)(m0 + 64 + (tid >> 2)) * K + (tid & 3) * 8;
    const __half* Bsrc0 = Wt + (size_t)(n0 + (tid >> 2)) * K + (tid & 3) * 8;
    const __half* Bsrc1 = Wt + (size_t)(n0 + 64 + (tid >> 2)) * K + (tid & 3) * 8;
    uint32_t adst0 = as_u + tid * 16;
    uint32_t adst1 = as_u + tid * 16 + 4096;
    uint32_t bdst0 = bs_u + tid * 16;
    uint32_t bdst1 = bs_u + tid * 16 + 4096;

    float acc[4][4][4];
    #pragma unroll
    for (int a = 0; a < 4; a++)
        #pragma unroll
        for (int b = 0; b < 4; b++)
            #pragma unroll
            for (int c = 0; c < 4; c++) acc[a][b][c] = 0.0f;

    const int nt = K >> 5;

    #pragma unroll
    for (int s = 0; s < STAGES - 1; s++) {
        uint32_t so = (uint32_t)(s * 8192);
        cp16(adst0 + so, Asrc0 + s * 32);
        cp16(adst1 + so, Asrc1 + s * 32);
        cp16(bdst0 + so, Bsrc0 + s * 32);
        cp16(bdst1 + so, Bsrc1 + s * 32);
        CP_COMMIT();
    }

    for (int t = 0; t < nt; t++) {
        CP_WAIT2();
        __syncthreads();

        int tn = t + STAGES - 1;
        if (tn < nt) {
            uint32_t so = (uint32_t)((tn & 3) * 8192);
            cp16(adst0 + so, Asrc0 + tn * 32);
            cp16(adst1 + so, Asrc1 + tn * 32);
            cp16(bdst0 + so, Bsrc0 + tn * 32);
            cp16(bdst1 + so, Bsrc1 + tn * 32);
        }
        CP_COMMIT();

        const __half* Ab = As + (t & 3) * 4096;
        const __half* Bb = Bs + (t & 3) * 4096;

        uint4 av0[4], av1[4], bv[4];
        #pragma unroll
        for (int mf = 0; mf < 4; mf++) {
            av0[mf] = *reinterpret_cast<const uint4*>(Ab + (wm + mf * 16 + rw) * 32 + tg * 8);
            av1[mf] = *reinterpret_cast<const uint4*>(Ab + (wm + mf * 16 + rw + 8) * 32 + tg * 8);
        }
        #pragma unroll
        for (int nf = 0; nf < 4; nf++)
            bv[nf] = *reinterpret_cast<const uint4*>(Bb + (wn + nf * 8 + rw) * 32 + tg * 8);

        #pragma unroll
        for (int mf = 0; mf < 4; mf++)
            #pragma unroll
            for (int nf = 0; nf < 4; nf++) {
                mma_f16(acc[mf][nf], av0[mf].x, av1[mf].x, av0[mf].y, av1[mf].y,
                        bv[nf].x, bv[nf].y);
                mma_f16(acc[mf][nf], av0[mf].z, av1[mf].z, av0[mf].w, av1[mf].w,
                        bv[nf].z, bv[nf].w);
            }
    }

    float alpha = (EPI == 2 || EPI == 5) ? *alpha_p : 0.0f;

    #pragma unroll
    for (int mf = 0; mf < 4; mf++) {
        int r0 = m0 + wm + mf * 16 + rw;
        #pragma unroll
        for (int nf = 0; nf < 4; nf++) {
            int col = n0 + wn + nf * 8 + 2 * tg;
            float bx = bias[col], by = bias[col + 1];
            float v0 = acc[mf][nf][0] + bx, v1 = acc[mf][nf][1] + by;
            float v2 = acc[mf][nf][2] + bx, v3 = acc[mf][nf][3] + by;
            if (EPI == 0) {
                *reinterpret_cast<float2*>(C + (size_t)r0 * N + col) = make_float2(v0, v1);
                *reinterpret_cast<float2*>(C + (size_t)(r0 + 8) * N + col) = make_float2(v2, v3);
            } else if (EPI == 1) {
                v0 = 0.5f * v0 * (1.0f + erff(v0 * 0.7071067811865475f));
                v1 = 0.5f * v1 * (1.0f + erff(v1 * 0.7071067811865475f));
                v2 = 0.5f * v2 * (1.0f + erff(v2 * 0.7071067811865475f));
                v3 = 0.5f * v3 * (1.0f + erff(v3 * 0.7071067811865475f));
                __half* Ch = reinterpret_cast<__half*>(C);
                int c0 = pk16(col), c1 = pk16(col + 1);
                Ch[(size_t)r0 * N + c0] = __float2half(v0);
                Ch[(size_t)r0 * N + c1] = __float2half(v1);
                Ch[(size_t)(r0 + 8) * N + c0] = __float2half(v2);
                Ch[(size_t)(r0 + 8) * N + c1] = __float2half(v3);
            } else if (EPI == 2 || EPI == 5) {
                float2 h0 = *reinterpret_cast<const float2*>(C + (size_t)r0 * N + col);
                float2 h1 = *reinterpret_cast<const float2*>(C + (size_t)(r0 + 8) * N + col);
                h0.x += alpha * v0; h0.y += alpha * v1;
                h1.x += alpha * v2; h1.y += alpha * v3;
                *reinterpret_cast<float2*>(C + (size_t)r0 * N + col) = h0;
                *reinterpret_cast<float2*>(C + (size_t)(r0 + 8) * N + col) = h1;
                if (EPI == 5) {
                    int c0 = pk16(col), c1 = pk16(col + 1);
                    g_y[(size_t)r0 * Ff + c0] = __float2half(h0.x);
                    g_y[(size_t)r0 * Ff + c1] = __float2half(h0.y);
                    g_y[(size_t)(r0 + 8) * Ff + c0] = __float2half(h1.x);
                    g_y[(size_t)(r0 + 8) * Ff + c1] = __float2half(h1.y);
                }
            } else if (EPI == 3) {
                int b0i = r0 / Ll, l0 = r0 % Ll;
                int b1i = (r0 + 8) / Ll, l1 = (r0 + 8) % Ll;
                C[(size_t)b0i * Cc * Ll + (size_t)col * Ll + l0] = v0;
                C[(size_t)b0i * Cc * Ll + (size_t)(col + 1) * Ll + l0] = v1;
                C[(size_t)b1i * Cc * Ll + (size_t)col * Ll + l1] = v2;
                C[(size_t)b1i * Cc * Ll + (size_t)(col + 1) * Ll + l1] = v3;
            } else { // EPI == 4: fp16 plain store
                __half* Ch = reinterpret_cast<__half*>(C);
                __half2* p0 = reinterpret_cast<__half2*>(Ch + (size_t)r0 * N + col);
                __half2* p1 = reinterpret_cast<__half2*>(Ch + (size_t)(r0 + 8) * N + col);
                *p0 = __floats2half2_rn(v0, v1);
                *p1 = __floats2half2_rn(v2, v3);
            }
        }
    }
}

// ---------------------------------------------------------------------------
// LayerNorm F=384: warp/token; output fp16 permuted
// ---------------------------------------------------------------------------
__global__ __launch_bounds__(256)
void ln_k(const float* __restrict__ x, const float* __restrict__ s,
          const float* __restrict__ bb, __half* __restrict__ y)
{
    int gw = (blockIdx.x * blockDim.x + threadIdx.x) >> 5;
    int lane = threadIdx.x & 31;
    if (gw >= Mrow) return;
    const float* xr = x + (size_t)gw * Ff;

    float v[12];
    float sum = 0.0f;
    #pragma unroll
    for (int i = 0; i < 12; i++) { v[i] = xr[lane + i * 32]; sum += v[i]; }
    #pragma unroll
    for (int o = 16; o > 0; o >>= 1) sum += __shfl_xor_sync(0xffffffffu, sum, o);
    float mean = sum * (1.0f / 384.0f);

    float var = 0.0f;
    #pragma unroll
    for (int i = 0; i < 12; i++) { float d = v[i] - mean; var += d * d; }
    #pragma unroll
    for (int o = 16; o > 0; o >>= 1) var += __shfl_xor_sync(0xffffffffu, var, o);
    var *= (1.0f / 384.0f);
    float rstd = rsqrtf(var + 1e-5f);

    __half* yr = y + (size_t)gw * Ff;
    #pragma unroll
    for (int i = 0; i < 12; i++) {
        int c = lane + i * 32;
        yr[pk16(c)] = __float2half((v[i] - mean) * rstd * s[c] + bb[c]);
    }
}

// ---------------------------------------------------------------------------
// Windowed attention; fp16 smem (half the traffic/footprint of fp32 version)
// ---------------------------------------------------------------------------
__global__ __launch_bounds__(256)
void attn_k(const __half* __restrict__ qkv, __half* __restrict__ o)
{
    __shared__ __align__(16) __half sh[WSz * 1152];
    __shared__ float sc[NHd][WSz * WSz];

    int bw = blockIdx.x;
    int m0 = bw * WSz;
    int tid = threadIdx.x;

    const uint4* src = reinterpret_cast<const uint4*>(qkv + (size_t)m0 * 1152);
    uint4* dst = reinterpret_cast<uint4*>(sh);
    for (int i = tid; i < WSz * 1152 / 8; i += 256) dst[i] = src[i];
    __syncthreads();

    int h = tid >> 5, lane = tid & 31;
    const float scale = 0.14433756729740643f;

    for (int idx = lane; idx < WSz * WSz; idx += 32) {
        int i = idx / WSz, j = idx % WSz;
        const __half2* q = reinterpret_cast<const __half2*>(sh + i * 1152 + h * Dh);
        const __half2* k = reinterpret_cast<const __half2*>(sh + j * 1152 + Ff + h * Dh);
        float d = 0.0f;
        #pragma unroll
        for (int t = 0; t < Dh / 2; t++) {
            float2 fq = __half22float2(q[t]);
            float2 fk = __half22float2(k[t]);
            d = fmaf(fq.x, fk.x, d);
            d = fmaf(fq.y, fk.y, d);
        }
        sc[h][idx] = d * scale;
    }
    __syncwarp();

    if (lane < WSz) {
        float* r = sc[h] + lane * WSz;
        float mx = r[0];
        #pragma unroll
        for (int j = 1; j < WSz; j++) mx = fmaxf(mx, r[j]);
        float sum = 0.0f;
        #pragma unroll
        for (int j = 0; j < WSz; j++) { float e = expf(r[j] - mx); r[j] = e; sum += e; }
        float inv = 1.0f / sum;
        #pragma unroll
        for (int j = 0; j < WSz; j++) r[j] *= inv;
    }
    __syncwarp();

    for (int idx = lane; idx < WSz * Dh; idx += 32) {
        int i = idx / Dh, d = idx % Dh;
        float a = 0.0f;
        #pragma unroll
        for (int j = 0; j < WSz; j++)
            a = fmaf(sc[h][i * WSz + j],
                     __half2float(sh[j * 1152 + 2 * Ff + h * Dh + d]), a);
        o[(size_t)(m0 + i) * Ff + pk16(h * Dh + d)] = __float2half(a);
    }
}

// ---------------------------------------------------------------------------
// Launch — ncu captures launch index 3 (0-based) = gemm_in
// ---------------------------------------------------------------------------
extern "C" void kernel_launch(void* const* d_in, const int* in_sizes, int n_in,
                              void* d_out, int out_size)
{
    const float* x       = (const float*)d_in[0];
    const float* embed_w = (const float*)d_in[1];
    const float* embed_b = (const float*)d_in[2];
    const float* in_w    = (const float*)d_in[3];
    const float* in_b    = (const float*)d_in[4];
    const float* ln1_s   = (const float*)d_in[5];
    const float* ln1_b   = (const float*)d_in[6];
    const float* qkv_w   = (const float*)d_in[7];
    const float* qkv_b   = (const float*)d_in[8];
    const float* proj_w  = (const float*)d_in[9];
    const float* proj_b  = (const float*)d_in[10];
    const float* ln2_s   = (const float*)d_in[11];
    const float* ln2_b   = (const float*)d_in[12];
    const float* ffn_w1  = (const float*)d_in[13];
    const float* ffn_b1  = (const float*)d_in[14];
    const float* ffn_w2  = (const float*)d_in[15];
    const float* ffn_b2  = (const float*)d_in[16];
    const float* re_alpha= (const float*)d_in[17];
    const float* out_w   = (const float*)d_in[18];
    const float* out_b   = (const float*)d_in[19];
    float* out = (float*)d_out;

    __half *xin, *y, *o, *mid, *wt, *qkv;
    float *h;
    cudaGetSymbolAddress((void**)&xin, g_xin);
    cudaGetSymbolAddress((void**)&h,   g_h);
    cudaGetSymbolAddress((void**)&y,   g_y);
    cudaGetSymbolAddress((void**)&qkv, g_qkv);
    cudaGetSymbolAddress((void**)&o,   g_o);
    cudaGetSymbolAddress((void**)&mid, g_mid);
    cudaGetSymbolAddress((void**)&wt,  g_wt);

    const int SMSZ = STAGES * 4096 * 2 * 2;   // 65536 bytes
    cudaFuncSetAttribute(gemm_mma<0>, cudaFuncAttributeMaxDynamicSharedMemorySize, SMSZ);
    cudaFuncSetAttribute(gemm_mma<1>, cudaFuncAttributeMaxDynamicSharedMemorySize, SMSZ);
    cudaFuncSetAttribute(gemm_mma<2>, cudaFuncAttributeMaxDynamicSharedMemorySize, SMSZ);
    cudaFuncSetAttribute(gemm_mma<3>, cudaFuncAttributeMaxDynamicSharedMemorySize, SMSZ);
    cudaFuncSetAttribute(gemm_mma<4>, cudaFuncAttributeMaxDynamicSharedMemorySize, SMSZ);
    cudaFuncSetAttribute(gemm_mma<5>, cudaFuncAttributeMaxDynamicSharedMemorySize, SMSZ);

    const int MT = Mrow / 128;   // 98
    const int LN_BLOCKS = Mrow * 32 / 256;
    dim3 tb(32, 8);

    // 0: build_xin
    build_xin_k<<<(Mrow * 768 + 255) / 256, 256>>>(x, embed_w, embed_b);
    // 1: transpose group 0 (in, qkv, proj)
    transpose_grp0<<<GRP0_BLOCKS, tb>>>(in_w, qkv_w, proj_w, wt);
    // 2: transpose group 1 (ffn1, ffn2, out)
    transpose_grp1<<<GRP1_BLOCKS, tb>>>(ffn_w1, ffn_w2, out_w, wt);
    // 3: input projection  <-- ncu capture target
    gemm_mma<0><<<dim3(Ff / 128, MT), 256, SMSZ>>>(xin, wt + W_IN_OFF, in_b, h, Ee + Cc, Ff, nullptr);
    // 4: ln1 blk0
    ln_k<<<LN_BLOCKS, 256>>>(h, ln1_s, ln1_b, y);
    // 5: qkv GEMM blk0
    gemm_mma<4><<<dim3(3 * Ff / 128, MT), 256, SMSZ>>>(
        y, wt + W_QKV_OFF, qkv_b, (float*)qkv, Ff, 3 * Ff, nullptr);

    for (int blk = 0; blk < NBk; blk++) {
        if (blk > 0) {
            ln_k<<<LN_BLOCKS, 256>>>(h, ln1_s + blk * Ff, ln1_b + blk * Ff, y);
            gemm_mma<4><<<dim3(3 * Ff / 128, MT), 256, SMSZ>>>(
                y, wt + W_QKV_OFF + (size_t)blk * Ff * 3 * Ff, qkv_b + (size_t)blk * 3 * Ff,
                (float*)qkv, Ff, 3 * Ff, nullptr);
        }

        attn_k<<<Bn * (Ll / WSz), 256>>>(qkv, o);

        gemm_mma<2><<<dim3(Ff / 128, MT), 256, SMSZ>>>(
            o, wt + W_PROJ_OFF + (size_t)blk * Ff * Ff, proj_b + (size_t)blk * Ff,
            h, Ff, Ff, re_alpha + blk);

        ln_k<<<LN_BLOCKS, 256>>>(h, ln2_s + blk * Ff, ln2_b + blk * Ff, y);

        gemm_mma<1><<<dim3(FFNe / 128, MT), 256, SMSZ>>>(
            y, wt + W_FFN1_OFF + (size_t)blk * Ff * FFNe, ffn_b1 + (size_t)blk * FFNe,
            (float*)mid, Ff, FFNe, nullptr);

        if (blk == NBk - 1) {
            gemm_mma<5><<<dim3(Ff / 128, MT), 256, SMSZ>>>(
                mid, wt + W_FFN2_OFF + (size_t)blk * FFNe * Ff, ffn_b2 + (size_t)blk * Ff,
                h, FFNe, Ff, re_alpha + blk);
        } else {
            gemm_mma<2><<<dim3(Ff / 128, MT), 256, SMSZ>>>(
                mid, wt + W_FFN2_OFF + (size_t)blk * FFNe * Ff, ffn_b2 + (size_t)blk * Ff,
                h, FFNe, Ff, re_alpha + blk);
        }
    }

    // output projection + transpose to [B, C, H, W]
    gemm_mma<3><<<dim3(Cc / 128, MT), 256, SMSZ>>>(y, wt + W_OUT_OFF, out_b, out, Ff, Cc, nullptr);
}